// round 16
// baseline (speedup 1.0000x reference)
#include <cuda_runtime.h>
#include <cuda_bf16.h>
#include <cuda_fp16.h>
#include <math.h>
#include <stdint.h>

#define B_    2
#define T_    2048
#define DIM_  2048
#define NH_   16
#define NKV_  4
#define HD_   128
#define KD_   512
#define GQ_   (NH_ / NKV_)
#define EPS_  1.1920928955078125e-07f

// ---------------- scratch ----------------------------------------------------
__device__ float g_cos[T_ * (HD_ / 2)];
__device__ float g_sin[T_ * (HD_ / 2)];
__device__ __half g_xH[(size_t)B_ * T_ * DIM_];
__device__ __half g_wqH[(size_t)DIM_ * DIM_];
__device__ __half g_wkH[(size_t)KD_ * DIM_];
__device__ __half g_wvH[(size_t)KD_ * DIM_];
__device__ __half g_wpH[(size_t)DIM_ * DIM_];
__device__ __half g_qH[(size_t)B_ * T_ * DIM_];
__device__ __half g_kH[(size_t)B_ * T_ * KD_];
__device__ __half g_vH[(size_t)B_ * T_ * KD_];
__device__ __half g_yH[(size_t)B_ * T_ * DIM_];

// ---------------- helpers ----------------------------------------------------
__device__ __forceinline__ uint32_t smem_u32(const void* p) {
    uint32_t a;
    asm("{ .reg .u64 t; cvta.to.shared.u64 t, %1; cvt.u32.u64 %0, t; }"
        : "=r"(a) : "l"(p));
    return a;
}
__device__ __forceinline__ float ex2(float x) {
    float r;
    asm("ex2.approx.ftz.f32 %0, %1;" : "=f"(r) : "f"(x));
    return r;
}
__device__ __forceinline__ void mma_f16(float* d, const uint32_t* a, const uint32_t* b) {
    asm volatile("mma.sync.aligned.m16n8k16.row.col.f32.f16.f16.f32 "
        "{%0,%1,%2,%3}, {%4,%5,%6,%7}, {%8,%9}, {%0,%1,%2,%3};"
        : "+f"(d[0]), "+f"(d[1]), "+f"(d[2]), "+f"(d[3])
        : "r"(a[0]), "r"(a[1]), "r"(a[2]), "r"(a[3]), "r"(b[0]), "r"(b[1]));
}
__device__ __forceinline__ void ldsm_x4(uint32_t* r, uint32_t addr) {
    asm volatile("ldmatrix.sync.aligned.m8n8.x4.shared.b16 {%0,%1,%2,%3}, [%4];"
        : "=r"(r[0]), "=r"(r[1]), "=r"(r[2]), "=r"(r[3]) : "r"(addr));
}
__device__ __forceinline__ void ldsm_x4_t(uint32_t* r, uint32_t addr) {
    asm volatile("ldmatrix.sync.aligned.m8n8.x4.trans.shared.b16 {%0,%1,%2,%3}, [%4];"
        : "=r"(r[0]), "=r"(r[1]), "=r"(r[2]), "=r"(r[3]) : "r"(addr));
}
__device__ __forceinline__ void cp16(uint32_t dst, const void* src) {
    asm volatile("cp.async.cg.shared.global [%0], [%1], 16;" :: "r"(dst), "l"(src));
}
#define CP_COMMIT() asm volatile("cp.async.commit_group;" ::: "memory")
#define CP_WAIT0()  asm volatile("cp.async.wait_group 0;" ::: "memory")
#define CP_WAIT2()  asm volatile("cp.async.wait_group 2;" ::: "memory")

__device__ __forceinline__ uint2 tohalf4(float4 f) {
    __half2 h0 = __floats2half2_rn(f.x, f.y);
    __half2 h1 = __floats2half2_rn(f.z, f.w);
    return make_uint2(*(uint32_t*)&h0, *(uint32_t*)&h1);
}
#define NEG_INF __int_as_float(0xff800000)

// ---------------- RoPE tables ------------------------------------------------
__global__ void rope_table_kernel() {
    int idx = blockIdx.x * blockDim.x + threadIdx.x;
    if (idx >= T_ * (HD_ / 2)) return;
    int t = idx >> 6;
    int i = idx & 63;
    double base = 10000.0;
    if (T_ > 1024)
        base = 10000.0 * pow((double)T_ / 1024.0, (double)HD_ / (double)(HD_ - 2));
    double f = pow(base, -((double)(2 * i)) / (double)HD_);
    double a = (double)t * f;
    g_cos[idx] = (float)cos(a);
    g_sin[idx] = (float)sin(a);
}

// ---------------- operand prep: fp32 -> fp16, 4-way ILP ------------------------
#define S_X   (B_ * T_ * DIM_ / 4)
#define S_WQ  (DIM_ * DIM_ / 4)
#define S_WK  (KD_ * DIM_ / 4)
#define SPLIT_TOT (S_X + S_WQ + S_WK + S_WK + S_WQ)

__device__ __forceinline__ void split_one(int i,
    const float* x, const float* Wq, const float* Wk,
    const float* Wv, const float* Wp)
{
    if (i < S_X)  { ((uint2*)g_xH)[i]  = tohalf4(((const float4*)x)[i]);  return; }
    i -= S_X;
    if (i < S_WQ) { ((uint2*)g_wqH)[i] = tohalf4(((const float4*)Wq)[i]); return; }
    i -= S_WQ;
    if (i < S_WK) { ((uint2*)g_wkH)[i] = tohalf4(((const float4*)Wk)[i]); return; }
    i -= S_WK;
    if (i < S_WK) { ((uint2*)g_wvH)[i] = tohalf4(((const float4*)Wv)[i]); return; }
    i -= S_WK;
    ((uint2*)g_wpH)[i] = tohalf4(((const float4*)Wp)[i]);
}

__global__ void split_all_kernel(const float* __restrict__ x,
                                 const float* __restrict__ Wq,
                                 const float* __restrict__ Wk,
                                 const float* __restrict__ Wv,
                                 const float* __restrict__ Wp)
{
    int base = blockIdx.x * 1024 + threadIdx.x;
    #pragma unroll
    for (int k = 0; k < 4; ++k) {
        int i = base + k * 256;
        if (i < SPLIT_TOT) split_one(i, x, Wq, Wk, Wv, Wp);
    }
}

// ---------------- 1-term fp16 GEMM body (512 thr, 4-stage, frag-pipelined) -----
#define HST     144
#define HPART   (128 * HST)
#define HSTAGE  (2 * HPART)
#define HSMEM   (4 * HSTAGE)

template<int KIND>
__device__ __forceinline__ void gemm1_body(
    const __half* __restrict__ A, const __half* __restrict__ W,
    float* __restrict__ C, __half* __restrict__ Ch,
    int N, int K, int bm, int bn, float post_mul)
{
    extern __shared__ char sm[];
    const uint32_t sb = smem_u32(sm);
    const int tid = threadIdx.x, wid = tid >> 5, lane = tid & 31;
    const int wm = wid & 3, wn = wid >> 2;

    float acc[2][4][4];
    #pragma unroll
    for (int i = 0; i < 2; ++i)
        #pragma unroll
        for (int j = 0; j < 4; ++j)
            #pragma unroll
            for (int q = 0; q < 4; ++q) acc[i][j][q] = 0.f;

    const int niter = K / 64;

    auto load_stage = [&](int it, int buf) {
        const int k0 = it * 64;
        const uint32_t s = sb + buf * HSTAGE;
        #pragma unroll
        for (int p = 0; p < 4; ++p) {
            int idx  = tid + p * 512;
            int part = idx >> 10;
            int r    = (idx >> 3) & 127;
            int c    = idx & 7;
            const __half* src = part ? W : A;
            int rowg = (part ? bn : bm) + r;
            cp16(s + part * HPART + r * HST + c * 16,
                 src + (size_t)rowg * K + k0 + c * 8);
        }
    };

    load_stage(0, 0); CP_COMMIT();
    load_stage(1, 1); CP_COMMIT();
    load_stage(2, 2); CP_COMMIT();

    const uint32_t ra_base = (wm * 32 + (lane & 15)) * HST + ((lane >> 4) << 4);
    const uint32_t rb_base = HPART
        + (wn * 32 + (lane & 7) + ((lane >> 4) << 3)) * HST
        + (((lane >> 3) & 1) << 4);

    for (int it = 0; it < niter; ++it) {
        const int buf = it & 3;
        CP_WAIT2();
        __syncthreads();
        if (it + 3 < niter) { load_stage(it + 3, (it + 3) & 3); CP_COMMIT(); }

        const uint32_t sbuf = sb + buf * HSTAGE;
        // fragment double-buffering: load ks+1 while computing ks
        uint32_t a[2][2][4], b[2][2][4];
        #pragma unroll
        for (int mt = 0; mt < 2; ++mt)
            ldsm_x4(a[0][mt], sbuf + ra_base + mt * 16 * HST);
        #pragma unroll
        for (int pr = 0; pr < 2; ++pr)
            ldsm_x4(b[0][pr], sbuf + rb_base + pr * 16 * HST);

        #pragma unroll
        for (int ks = 0; ks < 4; ++ks) {
            const int cur = ks & 1;
            if (ks < 3) {
                const uint32_t ko = (ks + 1) * 32;
                #pragma unroll
                for (int mt = 0; mt < 2; ++mt)
                    ldsm_x4(a[cur ^ 1][mt], sbuf + ra_base + mt * 16 * HST + ko);
                #pragma unroll
                for (int pr = 0; pr < 2; ++pr)
                    ldsm_x4(b[cur ^ 1][pr], sbuf + rb_base + pr * 16 * HST + ko);
            }
            #pragma unroll
            for (int mt = 0; mt < 2; ++mt)
                #pragma unroll
                for (int nt = 0; nt < 4; ++nt)
                    mma_f16(acc[mt][nt], a[cur][mt], b[cur][nt >> 1] + (nt & 1) * 2);
        }
        __syncthreads();
    }

    if (KIND == 0 || KIND == 1) {
        #pragma unroll
        for (int mt = 0; mt < 2; ++mt)
            #pragma unroll
            for (int nt = 0; nt < 4; ++nt) {
                int row = bm + wm * 32 + mt * 16 + (lane >> 2);
                int col = bn + wn * 32 + nt * 8 + 2 * (lane & 3);
                if (KIND == 1) {
                    __half2 u0 = __floats2half2_rn(acc[mt][nt][0], acc[mt][nt][1]);
                    __half2 u1 = __floats2half2_rn(acc[mt][nt][2], acc[mt][nt][3]);
                    *(uint32_t*)(Ch + (size_t)row * N + col)       = *(uint32_t*)&u0;
                    *(uint32_t*)(Ch + (size_t)(row + 8) * N + col) = *(uint32_t*)&u1;
                } else {
                    *(float2*)(C + (size_t)row * N + col) =
                        make_float2(acc[mt][nt][0], acc[mt][nt][1]);
                    *(float2*)(C + (size_t)(row + 8) * N + col) =
                        make_float2(acc[mt][nt][2], acc[mt][nt][3]);
                }
            }
        return;
    }

    // ---- KIND == 2: fused RMSNorm + RoPE epilogue (tile = one head) ----
    float* ssq_sm = (float*)sm;
    float* tile   = (float*)(sm + 2048);           // [128][132]

    float ssq[2][2];
    #pragma unroll
    for (int mt = 0; mt < 2; ++mt)
        #pragma unroll
        for (int hf = 0; hf < 2; ++hf) {
            float s = 0.f;
            #pragma unroll
            for (int nt = 0; nt < 4; ++nt) {
                float v0 = acc[mt][nt][hf * 2 + 0];
                float v1 = acc[mt][nt][hf * 2 + 1];
                s += v0 * v0 + v1 * v1;
            }
            s += __shfl_xor_sync(0xffffffffu, s, 1);
            s += __shfl_xor_sync(0xffffffffu, s, 2);
            ssq[mt][hf] = s;
        }
    if ((lane & 3) == 0) {
        #pragma unroll
        for (int mt = 0; mt < 2; ++mt)
            #pragma unroll
            for (int hf = 0; hf < 2; ++hf) {
                int row = wm * 32 + mt * 16 + hf * 8 + (lane >> 2);
                ssq_sm[row * 4 + wn] = ssq[mt][hf];
            }
    }
    __syncthreads();

    #pragma unroll
    for (int mt = 0; mt < 2; ++mt)
        #pragma unroll
        for (int hf = 0; hf < 2; ++hf) {
            int row = wm * 32 + mt * 16 + hf * 8 + (lane >> 2);
            float tot = ssq_sm[row * 4 + 0] + ssq_sm[row * 4 + 1]
                      + ssq_sm[row * 4 + 2] + ssq_sm[row * 4 + 3];
            float rr = rsqrtf(tot * (1.f / HD_) + EPS_) * post_mul;
            #pragma unroll
            for (int nt = 0; nt < 4; ++nt) {
                int col = wn * 32 + nt * 8 + 2 * (lane & 3);
                tile[row * 132 + col]     = acc[mt][nt][hf * 2 + 0] * rr;
                tile[row * 132 + col + 1] = acc[mt][nt][hf * 2 + 1] * rr;
            }
        }
    __syncthreads();

    #pragma unroll
    for (int mt = 0; mt < 2; ++mt)
        #pragma unroll
        for (int hf = 0; hf < 2; ++hf) {
            int row = wm * 32 + mt * 16 + hf * 8 + (lane >> 2);
            int t   = (bm + row) & (T_ - 1);
            #pragma unroll
            for (int nt = 0; nt < 4; ++nt) {
                int col = wn * 32 + nt * 8 + 2 * (lane & 3);
                float o[2];
                #pragma unroll
                for (int e = 0; e < 2; ++e) {
                    int c0 = col + e;
                    float own = tile[row * 132 + c0];
                    float par = tile[row * 132 + (c0 ^ 64)];
                    int i = c0 & 63;
                    float cs = g_cos[t * 64 + i];
                    float sn = g_sin[t * 64 + i];
                    o[e] = (c0 < 64) ? (own * cs + par * sn)
                                     : (own * cs - par * sn);
                }
                __half2 u = __floats2half2_rn(o[0], o[1]);
                *(uint32_t*)(Ch + (size_t)(bm + row) * N + bn + col) = *(uint32_t*)&u;
            }
        }
}

__global__ void __launch_bounds__(512, 1) gemm_qkv(
    const __half* __restrict__ xH,
    const __half* __restrict__ wq, const __half* __restrict__ wk,
    const __half* __restrict__ wv, const float* __restrict__ qg,
    __half* __restrict__ qO, __half* __restrict__ kO, __half* __restrict__ vO)
{
    const int bx = blockIdx.x;
    const float QMUL = 0.08838834764831845f * 1.44269504088896340736f;
    if (bx < 16) {
        float pm = qg[bx] * QMUL;
        gemm1_body<2>(xH, wq, nullptr, qO, DIM_, DIM_,
                      blockIdx.y * 128, bx * 128, pm);
    } else if (bx < 20) {
        gemm1_body<2>(xH, wk, nullptr, kO, KD_, DIM_,
                      blockIdx.y * 128, (bx - 16) * 128, 1.0f);
    } else {
        gemm1_body<1>(xH, wv, nullptr, vO, KD_, DIM_,
                      blockIdx.y * 128, (bx - 20) * 128, 1.0f);
    }
}

__global__ void __launch_bounds__(512, 1) gemm_out(
    const __half* __restrict__ A, const __half* __restrict__ W,
    float* __restrict__ C, int N, int K)
{
    gemm1_body<0>(A, W, C, nullptr, N, K, blockIdx.y * 128, blockIdx.x * 128, 1.0f);
}

// ---------------- flash attention: fp16, 128-key KV tiles ----------------------
#define FST     272
#define QT      (128 * FST)
#define KVP2    (128 * FST)
#define STG2    (2 * KVP2)
#define FSMEM2  (QT + 2 * STG2)      // 174080

__global__ void __launch_bounds__(256, 1) flash_mma(
    const __half* __restrict__ qH, const __half* __restrict__ kH,
    const __half* __restrict__ vH, __half* __restrict__ y)
{
    extern __shared__ char sm[];
    const uint32_t sb = smem_u32(sm);
    const int tid = threadIdx.x, wid = tid >> 5, lane = tid & 31;
    const int itq = (gridDim.x - 1) - blockIdx.x;
    const int h = blockIdx.y, b = blockIdx.z;
    const int kvh = h / GQ_;
    const int t0q = itq * 128;

    #pragma unroll
    for (int p = 0; p < 8; ++p) {
        int idx = tid + p * 256;
        int r = (idx >> 4) & 127, c = idx & 15;
        cp16(sb + r * FST + c * 16,
             qH + ((size_t)(b * T_ + t0q + r) * NH_ + h) * HD_ + c * 8);
    }
    #pragma unroll
    for (int p = 0; p < 16; ++p) {
        int idx = tid + p * 256;
        int part = idx >> 11;
        int r = (idx >> 4) & 127, c = idx & 15;
        const __half* src = part ? vH : kH;
        cp16(sb + QT + part * KVP2 + r * FST + c * 16,
             src + ((size_t)(b * T_ + r) * NKV_ + kvh) * HD_ + c * 8);
    }
    CP_COMMIT();
    CP_WAIT0();
    __syncthreads();

    uint32_t QF[8][4];
    #pragma unroll
    for (int ks = 0; ks < 8; ++ks) {
        uint32_t ra = sb + (wid * 16 + (lane & 15)) * FST
                    + ks * 32 + ((lane >> 4) << 4);
        ldsm_x4(QF[ks], ra);
    }

    float m0 = NEG_INF, m1 = NEG_INF, l0 = 0.f, l1 = 0.f;
    float O[16][4];
    #pragma unroll
    for (int nt = 0; nt < 16; ++nt)
        #pragma unroll
        for (int j = 0; j < 4; ++j) O[nt][j] = 0.f;

    const int row_a = t0q + wid * 16 + (lane >> 2);

    for (int jt = 0; jt <= itq; ++jt) {
        const int buf = jt & 1;
        if (jt > 0) { CP_WAIT0(); __syncthreads(); }
        if (jt + 1 <= itq) {
            const int t0n = (jt + 1) * 128;
            #pragma unroll
            for (int p = 0; p < 16; ++p) {
                int idx = tid + p * 256;
                int part = idx >> 11;
                int r = (idx >> 4) & 127, c = idx & 15;
                const __half* src = part ? vH : kH;
                cp16(sb + QT + (buf ^ 1) * STG2 + part * KVP2 + r * FST + c * 16,
                     src + ((size_t)(b * T_ + t0n + r) * NKV_ + kvh) * HD_ + c * 8);
            }
            CP_COMMIT();
        }

        const uint32_t base_k = sb + QT + buf * STG2;
        const uint32_t base_v = base_k + KVP2;
        const int t0k = jt * 128;

        float S[16][4];
        #pragma unroll
        for (int nt = 0; nt < 16; ++nt)
            #pragma unroll
            for (int j = 0; j < 4; ++j) S[nt][j] = 0.f;

        #pragma unroll
        for (int ks = 0; ks < 8; ++ks) {
            const uint32_t rk = base_k + ks * 32 + (((lane >> 3) & 1) << 4)
                              + ((lane & 7) + ((lane >> 4) << 3)) * FST;
            uint32_t bh[2][4];
            ldsm_x4(bh[0], rk);
            #pragma unroll
            for (int ntp = 0; ntp < 8; ++ntp) {
                if (ntp < 7)
                    ldsm_x4(bh[(ntp + 1) & 1], rk + (ntp + 1) * 16 * FST);
                mma_f16(S[2 * ntp],     QF[ks], bh[ntp & 1]);
                mma_f16(S[2 * ntp + 1], QF[ks], bh[ntp & 1] + 2);
            }
        }

        const bool diag = (jt == itq);
        float ml0 = NEG_INF, ml1 = NEG_INF;
        #pragma unroll
        for (int nt = 0; nt < 16; ++nt) {
            int c = t0k + nt * 8 + 2 * (lane & 3);
            if (diag) {
                if (c     > row_a)     S[nt][0] = NEG_INF;
                if (c + 1 > row_a)     S[nt][1] = NEG_INF;
                if (c     > row_a + 8) S[nt][2] = NEG_INF;
                if (c + 1 > row_a + 8) S[nt][3] = NEG_INF;
            }
            ml0 = fmaxf(ml0, fmaxf(S[nt][0], S[nt][1]));
            ml1 = fmaxf(ml1, fmaxf(S[nt][2], S[nt][3]));
        }
        ml0 = fmaxf(ml0, __shfl_xor_sync(0xffffffffu, ml0, 1));
        ml0 = fmaxf(ml0, __shfl_xor_sync(0xffffffffu, ml0, 2));
        ml1 = fmaxf(ml1, __shfl_xor_sync(0xffffffffu, ml1, 1));
        ml1 = fmaxf(ml1, __shfl_xor_sync(0xffffffffu, ml1, 2));

        float mn0 = fmaxf(m0, ml0), mn1 = fmaxf(m1, ml1);
        float es0 = ex2(m0 - mn0);
        float es1 = ex2(m1 - mn1);
        m0 = mn0; m1 = mn1;
        #pragma unroll
        for (int nt = 0; nt < 16; ++nt) {
            O[nt][0] *= es0; O[nt][1] *= es0;
            O[nt][2] *= es1; O[nt][3] *= es1;
        }

        float sum0 = 0.f, sum1 = 0.f;
        #pragma unroll
        for (int half = 0; half < 2; ++half) {
            uint32_t PH[16];
            #pragma unroll
            for (int ntl = 0; ntl < 8; ++ntl) {
                int nt = half * 8 + ntl;
                float p0 = ex2(S[nt][0] - mn0);
                float p1 = ex2(S[nt][1] - mn0);
                float p2 = ex2(S[nt][2] - mn1);
                float p3 = ex2(S[nt][3] - mn1);
                sum0 += p0 + p1;  sum1 += p2 + p3;
                __half2 hA = __floats2half2_rn(p0, p1);
                __half2 hB = __floats2half2_rn(p2, p3);
                PH[2 * ntl]     = *(uint32_t*)&hA;
                PH[2 * ntl + 1] = *(uint32_t*)&hB;
            }
            #pragma unroll
            for (int kt = 0; kt < 4; ++kt) {
                uint32_t pa[4] = { PH[4*kt], PH[4*kt+1], PH[4*kt+2], PH[4*kt+3] };
                #pragma unroll
                for (int ntp = 0; ntp < 8; ++ntp) {
                    uint32_t bh[4];
                    uint32_t rv = base_v
                                + (half * 64 + kt * 16 + (lane & 7) + (lane & 8)) * FST
                                + ntp * 32 + ((lane >> 4) << 4);
                    ldsm_x4_t(bh, rv);
                    mma_f16(O[2 * ntp],     pa, bh);
                    mma_f16(O[2 * ntp + 1], pa, bh + 2);
                }
            }
        }
        sum0 += __shfl_xor_sync(0xffffffffu, sum0, 1);
        sum0 += __shfl_xor_sync(0xffffffffu, sum0, 2);
        sum1 += __shfl_xor_sync(0xffffffffu, sum1, 1);
        sum1 += __shfl_xor_sync(0xffffffffu, sum1, 2);
        l0 = l0 * es0 + sum0;
        l1 = l1 * es1 + sum1;
    }

    float inv0 = 1.f / l0, inv1 = 1.f / l1;
    #pragma unroll
    for (int nt = 0; nt < 16; ++nt) {
        int c = nt * 8 + 2 * (lane & 3);
        size_t baseA = ((size_t)(b * T_ + row_a) * NH_ + h) * HD_ + c;
        size_t baseB = ((size_t)(b * T_ + row_a + 8) * NH_ + h) * HD_ + c;
        __half2 uA = __floats2half2_rn(O[nt][0] * inv0, O[nt][1] * inv0);
        __half2 uB = __floats2half2_rn(O[nt][2] * inv1, O[nt][3] * inv1);
        *(uint32_t*)(y + baseA) = *(uint32_t*)&uA;
        *(uint32_t*)(y + baseB) = *(uint32_t*)&uB;
    }
}

// ---------------------------------------------------------------------------
extern "C" void kernel_launch(void* const* d_in, const int* in_sizes, int n_in,
                              void* d_out, int out_size)
{
    const float* x  = (const float*)d_in[0];
    const float* Wq = (const float*)d_in[1];
    const float* Wk = (const float*)d_in[2];
    const float* Wv = (const float*)d_in[3];
    const float* Wp = (const float*)d_in[4];
    const float* qg = (const float*)d_in[5];
    float* out = (float*)d_out;

    __half *xH, *wqH, *wkH, *wvH, *wpH, *qh16, *kh16, *vh16, *yH;
    cudaGetSymbolAddress((void**)&xH,  g_xH);
    cudaGetSymbolAddress((void**)&wqH, g_wqH);
    cudaGetSymbolAddress((void**)&wkH, g_wkH);
    cudaGetSymbolAddress((void**)&wvH, g_wvH);
    cudaGetSymbolAddress((void**)&wpH, g_wpH);
    cudaGetSymbolAddress((void**)&qh16, g_qH);
    cudaGetSymbolAddress((void**)&kh16, g_kH);
    cudaGetSymbolAddress((void**)&vh16, g_vH);
    cudaGetSymbolAddress((void**)&yH,  g_yH);

    cudaFuncSetAttribute(gemm_qkv, cudaFuncAttributeMaxDynamicSharedMemorySize, HSMEM);
    cudaFuncSetAttribute(gemm_out, cudaFuncAttributeMaxDynamicSharedMemorySize, HSMEM);
    cudaFuncSetAttribute(flash_mma, cudaFuncAttributeMaxDynamicSharedMemorySize, FSMEM2);

    rope_table_kernel<<<(T_ * 64 + 255) / 256, 256>>>();
    split_all_kernel<<<(SPLIT_TOT + 1023) / 1024, 256>>>(x, Wq, Wk, Wv, Wp);

    gemm_qkv<<<dim3(24, (B_ * T_) / 128), 512, HSMEM>>>(
        xH, wqH, wkH, wvH, qg, qh16, kh16, vh16);

    flash_mma<<<dim3(T_ / 128, NH_, B_), 256, FSMEM2>>>(qh16, kh16, vh16, yH);

    gemm_out<<<dim3(DIM_ / 128, (B_ * T_) / 128), 512, HSMEM>>>(
        yH, wpH, out, DIM_, DIM_);
}

// round 17
// speedup vs baseline: 1.0275x; 1.0275x over previous
#include <cuda_runtime.h>
#include <cuda_bf16.h>
#include <cuda_fp16.h>
#include <math.h>
#include <stdint.h>

#define B_    2
#define T_    2048
#define DIM_  2048
#define NH_   16
#define NKV_  4
#define HD_   128
#define KD_   512
#define GQ_   (NH_ / NKV_)
#define EPS_  1.1920928955078125e-07f

// ---------------- scratch ----------------------------------------------------
__device__ float g_cos[T_ * (HD_ / 2)];
__device__ float g_sin[T_ * (HD_ / 2)];
__device__ __half g_xH[(size_t)B_ * T_ * DIM_];
__device__ __half g_wqH[(size_t)DIM_ * DIM_];
__device__ __half g_wkH[(size_t)KD_ * DIM_];
__device__ __half g_wvH[(size_t)KD_ * DIM_];
__device__ __half g_wpH[(size_t)DIM_ * DIM_];
__device__ __half g_qH[(size_t)B_ * T_ * DIM_];
__device__ __half g_kH[(size_t)B_ * T_ * KD_];
__device__ __half g_vH[(size_t)B_ * T_ * KD_];
__device__ __half g_yH[(size_t)B_ * T_ * DIM_];

// ---------------- helpers ----------------------------------------------------
__device__ __forceinline__ uint32_t smem_u32(const void* p) {
    uint32_t a;
    asm("{ .reg .u64 t; cvta.to.shared.u64 t, %1; cvt.u32.u64 %0, t; }"
        : "=r"(a) : "l"(p));
    return a;
}
__device__ __forceinline__ float ex2(float x) {
    float r;
    asm("ex2.approx.ftz.f32 %0, %1;" : "=f"(r) : "f"(x));
    return r;
}
__device__ __forceinline__ void mma_f16(float* d, const uint32_t* a, const uint32_t* b) {
    asm volatile("mma.sync.aligned.m16n8k16.row.col.f32.f16.f16.f32 "
        "{%0,%1,%2,%3}, {%4,%5,%6,%7}, {%8,%9}, {%0,%1,%2,%3};"
        : "+f"(d[0]), "+f"(d[1]), "+f"(d[2]), "+f"(d[3])
        : "r"(a[0]), "r"(a[1]), "r"(a[2]), "r"(a[3]), "r"(b[0]), "r"(b[1]));
}
__device__ __forceinline__ void ldsm_x4(uint32_t* r, uint32_t addr) {
    asm volatile("ldmatrix.sync.aligned.m8n8.x4.shared.b16 {%0,%1,%2,%3}, [%4];"
        : "=r"(r[0]), "=r"(r[1]), "=r"(r[2]), "=r"(r[3]) : "r"(addr));
}
__device__ __forceinline__ void ldsm_x4_t(uint32_t* r, uint32_t addr) {
    asm volatile("ldmatrix.sync.aligned.m8n8.x4.trans.shared.b16 {%0,%1,%2,%3}, [%4];"
        : "=r"(r[0]), "=r"(r[1]), "=r"(r[2]), "=r"(r[3]) : "r"(addr));
}
__device__ __forceinline__ void cp16(uint32_t dst, const void* src) {
    asm volatile("cp.async.cg.shared.global [%0], [%1], 16;" :: "r"(dst), "l"(src));
}
#define CP_COMMIT() asm volatile("cp.async.commit_group;" ::: "memory")
#define CP_WAIT0()  asm volatile("cp.async.wait_group 0;" ::: "memory")
#define CP_WAIT2()  asm volatile("cp.async.wait_group 2;" ::: "memory")

__device__ __forceinline__ uint2 tohalf4(float4 f) {
    __half2 h0 = __floats2half2_rn(f.x, f.y);
    __half2 h1 = __floats2half2_rn(f.z, f.w);
    return make_uint2(*(uint32_t*)&h0, *(uint32_t*)&h1);
}
#define NEG_INF __int_as_float(0xff800000)

// ---------------- RoPE tables ------------------------------------------------
__global__ void rope_table_kernel() {
    int idx = blockIdx.x * blockDim.x + threadIdx.x;
    if (idx >= T_ * (HD_ / 2)) return;
    int t = idx >> 6;
    int i = idx & 63;
    double base = 10000.0;
    if (T_ > 1024)
        base = 10000.0 * pow((double)T_ / 1024.0, (double)HD_ / (double)(HD_ - 2));
    double f = pow(base, -((double)(2 * i)) / (double)HD_);
    double a = (double)t * f;
    g_cos[idx] = (float)cos(a);
    g_sin[idx] = (float)sin(a);
}

// ---------------- operand prep: fp32 -> fp16, 4-way ILP ------------------------
#define S_X   (B_ * T_ * DIM_ / 4)
#define S_WQ  (DIM_ * DIM_ / 4)
#define S_WK  (KD_ * DIM_ / 4)
#define SPLIT_TOT (S_X + S_WQ + S_WK + S_WK + S_WQ)

__device__ __forceinline__ void split_one(int i,
    const float* x, const float* Wq, const float* Wk,
    const float* Wv, const float* Wp)
{
    if (i < S_X)  { ((uint2*)g_xH)[i]  = tohalf4(((const float4*)x)[i]);  return; }
    i -= S_X;
    if (i < S_WQ) { ((uint2*)g_wqH)[i] = tohalf4(((const float4*)Wq)[i]); return; }
    i -= S_WQ;
    if (i < S_WK) { ((uint2*)g_wkH)[i] = tohalf4(((const float4*)Wk)[i]); return; }
    i -= S_WK;
    if (i < S_WK) { ((uint2*)g_wvH)[i] = tohalf4(((const float4*)Wv)[i]); return; }
    i -= S_WK;
    ((uint2*)g_wpH)[i] = tohalf4(((const float4*)Wp)[i]);
}

__global__ void split_all_kernel(const float* __restrict__ x,
                                 const float* __restrict__ Wq,
                                 const float* __restrict__ Wk,
                                 const float* __restrict__ Wv,
                                 const float* __restrict__ Wp)
{
    int base = blockIdx.x * 1024 + threadIdx.x;
    #pragma unroll
    for (int k = 0; k < 4; ++k) {
        int i = base + k * 256;
        if (i < SPLIT_TOT) split_one(i, x, Wq, Wk, Wv, Wp);
    }
}

// ---------------- 1-term fp16 GEMM body (512 thr, 4-stage; R15 inner loop) -----
#define HST     144
#define HPART   (128 * HST)
#define HSTAGE  (2 * HPART)
#define HSMEM   (4 * HSTAGE)

template<int KIND>
__device__ __forceinline__ void gemm1_body(
    const __half* __restrict__ A, const __half* __restrict__ W,
    float* __restrict__ C, __half* __restrict__ Ch,
    int N, int K, int bm, int bn, float post_mul)
{
    extern __shared__ char sm[];
    const uint32_t sb = smem_u32(sm);
    const int tid = threadIdx.x, wid = tid >> 5, lane = tid & 31;
    const int wm = wid & 3, wn = wid >> 2;

    float acc[2][4][4];
    #pragma unroll
    for (int i = 0; i < 2; ++i)
        #pragma unroll
        for (int j = 0; j < 4; ++j)
            #pragma unroll
            for (int q = 0; q < 4; ++q) acc[i][j][q] = 0.f;

    const int niter = K / 64;

    auto load_stage = [&](int it, int buf) {
        const int k0 = it * 64;
        const uint32_t s = sb + buf * HSTAGE;
        #pragma unroll
        for (int p = 0; p < 4; ++p) {
            int idx  = tid + p * 512;
            int part = idx >> 10;
            int r    = (idx >> 3) & 127;
            int c    = idx & 7;
            const __half* src = part ? W : A;
            int rowg = (part ? bn : bm) + r;
            cp16(s + part * HPART + r * HST + c * 16,
                 src + (size_t)rowg * K + k0 + c * 8);
        }
    };

    load_stage(0, 0); CP_COMMIT();
    load_stage(1, 1); CP_COMMIT();
    load_stage(2, 2); CP_COMMIT();

    for (int it = 0; it < niter; ++it) {
        const int buf = it & 3;
        CP_WAIT2();
        __syncthreads();
        if (it + 3 < niter) { load_stage(it + 3, (it + 3) & 3); CP_COMMIT(); }

        const uint32_t sbuf = sb + buf * HSTAGE;
        #pragma unroll
        for (int ks = 0; ks < 4; ++ks) {
            uint32_t a[2][4], b[2][4];
            #pragma unroll
            for (int mt = 0; mt < 2; ++mt) {
                uint32_t ra = sbuf + (wm * 32 + mt * 16 + (lane & 15)) * HST
                            + ks * 32 + ((lane >> 4) << 4);
                ldsm_x4(a[mt], ra);
            }
            #pragma unroll
            for (int pr = 0; pr < 2; ++pr) {
                uint32_t rb = sbuf + HPART
                            + (wn * 32 + pr * 16 + (lane & 7) + ((lane >> 4) << 3)) * HST
                            + ks * 32 + (((lane >> 3) & 1) << 4);
                ldsm_x4(b[pr], rb);
            }
            #pragma unroll
            for (int mt = 0; mt < 2; ++mt)
                #pragma unroll
                for (int nt = 0; nt < 4; ++nt)
                    mma_f16(acc[mt][nt], a[mt], b[nt >> 1] + (nt & 1) * 2);
        }
        __syncthreads();
    }

    if (KIND == 0 || KIND == 1) {
        #pragma unroll
        for (int mt = 0; mt < 2; ++mt)
            #pragma unroll
            for (int nt = 0; nt < 4; ++nt) {
                int row = bm + wm * 32 + mt * 16 + (lane >> 2);
                int col = bn + wn * 32 + nt * 8 + 2 * (lane & 3);
                if (KIND == 1) {
                    __half2 u0 = __floats2half2_rn(acc[mt][nt][0], acc[mt][nt][1]);
                    __half2 u1 = __floats2half2_rn(acc[mt][nt][2], acc[mt][nt][3]);
                    *(uint32_t*)(Ch + (size_t)row * N + col)       = *(uint32_t*)&u0;
                    *(uint32_t*)(Ch + (size_t)(row + 8) * N + col) = *(uint32_t*)&u1;
                } else {
                    *(float2*)(C + (size_t)row * N + col) =
                        make_float2(acc[mt][nt][0], acc[mt][nt][1]);
                    *(float2*)(C + (size_t)(row + 8) * N + col) =
                        make_float2(acc[mt][nt][2], acc[mt][nt][3]);
                }
            }
        return;
    }

    // ---- KIND == 2: fused RMSNorm + RoPE epilogue (tile = one head) ----
    float* ssq_sm = (float*)sm;
    float* tile   = (float*)(sm + 2048);           // [128][132]

    float ssq[2][2];
    #pragma unroll
    for (int mt = 0; mt < 2; ++mt)
        #pragma unroll
        for (int hf = 0; hf < 2; ++hf) {
            float s = 0.f;
            #pragma unroll
            for (int nt = 0; nt < 4; ++nt) {
                float v0 = acc[mt][nt][hf * 2 + 0];
                float v1 = acc[mt][nt][hf * 2 + 1];
                s += v0 * v0 + v1 * v1;
            }
            s += __shfl_xor_sync(0xffffffffu, s, 1);
            s += __shfl_xor_sync(0xffffffffu, s, 2);
            ssq[mt][hf] = s;
        }
    if ((lane & 3) == 0) {
        #pragma unroll
        for (int mt = 0; mt < 2; ++mt)
            #pragma unroll
            for (int hf = 0; hf < 2; ++hf) {
                int row = wm * 32 + mt * 16 + hf * 8 + (lane >> 2);
                ssq_sm[row * 4 + wn] = ssq[mt][hf];
            }
    }
    __syncthreads();

    #pragma unroll
    for (int mt = 0; mt < 2; ++mt)
        #pragma unroll
        for (int hf = 0; hf < 2; ++hf) {
            int row = wm * 32 + mt * 16 + hf * 8 + (lane >> 2);
            float tot = ssq_sm[row * 4 + 0] + ssq_sm[row * 4 + 1]
                      + ssq_sm[row * 4 + 2] + ssq_sm[row * 4 + 3];
            float rr = rsqrtf(tot * (1.f / HD_) + EPS_) * post_mul;
            #pragma unroll
            for (int nt = 0; nt < 4; ++nt) {
                int col = wn * 32 + nt * 8 + 2 * (lane & 3);
                tile[row * 132 + col]     = acc[mt][nt][hf * 2 + 0] * rr;
                tile[row * 132 + col + 1] = acc[mt][nt][hf * 2 + 1] * rr;
            }
        }
    __syncthreads();

    #pragma unroll
    for (int mt = 0; mt < 2; ++mt)
        #pragma unroll
        for (int hf = 0; hf < 2; ++hf) {
            int row = wm * 32 + mt * 16 + hf * 8 + (lane >> 2);
            int t   = (bm + row) & (T_ - 1);
            #pragma unroll
            for (int nt = 0; nt < 4; ++nt) {
                int col = wn * 32 + nt * 8 + 2 * (lane & 3);
                float o[2];
                #pragma unroll
                for (int e = 0; e < 2; ++e) {
                    int c0 = col + e;
                    float own = tile[row * 132 + c0];
                    float par = tile[row * 132 + (c0 ^ 64)];
                    int i = c0 & 63;
                    float cs = g_cos[t * 64 + i];
                    float sn = g_sin[t * 64 + i];
                    o[e] = (c0 < 64) ? (own * cs + par * sn)
                                     : (own * cs - par * sn);
                }
                __half2 u = __floats2half2_rn(o[0], o[1]);
                *(uint32_t*)(Ch + (size_t)(bm + row) * N + bn + col) = *(uint32_t*)&u;
            }
        }
}

__global__ void __launch_bounds__(512, 1) gemm_qkv(
    const __half* __restrict__ xH,
    const __half* __restrict__ wq, const __half* __restrict__ wk,
    const __half* __restrict__ wv, const float* __restrict__ qg,
    __half* __restrict__ qO, __half* __restrict__ kO, __half* __restrict__ vO)
{
    const int bx = blockIdx.x;
    const float QMUL = 0.08838834764831845f * 1.44269504088896340736f;
    if (bx < 16) {
        float pm = qg[bx] * QMUL;
        gemm1_body<2>(xH, wq, nullptr, qO, DIM_, DIM_,
                      blockIdx.y * 128, bx * 128, pm);
    } else if (bx < 20) {
        gemm1_body<2>(xH, wk, nullptr, kO, KD_, DIM_,
                      blockIdx.y * 128, (bx - 16) * 128, 1.0f);
    } else {
        gemm1_body<1>(xH, wv, nullptr, vO, KD_, DIM_,
                      blockIdx.y * 128, (bx - 20) * 128, 1.0f);
    }
}

__global__ void __launch_bounds__(512, 1) gemm_out(
    const __half* __restrict__ A, const __half* __restrict__ W,
    float* __restrict__ C, int N, int K)
{
    gemm1_body<0>(A, W, C, nullptr, N, K, blockIdx.y * 128, blockIdx.x * 128, 1.0f);
}

// ---------------- flash attention: fp16, 128-key KV tiles (R16 S-loop) ---------
#define FST     272
#define QT      (128 * FST)
#define KVP2    (128 * FST)
#define STG2    (2 * KVP2)
#define FSMEM2  (QT + 2 * STG2)      // 174080

__global__ void __launch_bounds__(256, 1) flash_mma(
    const __half* __restrict__ qH, const __half* __restrict__ kH,
    const __half* __restrict__ vH, __half* __restrict__ y)
{
    extern __shared__ char sm[];
    const uint32_t sb = smem_u32(sm);
    const int tid = threadIdx.x, wid = tid >> 5, lane = tid & 31;
    const int itq = (gridDim.x - 1) - blockIdx.x;
    const int h = blockIdx.y, b = blockIdx.z;
    const int kvh = h / GQ_;
    const int t0q = itq * 128;

    #pragma unroll
    for (int p = 0; p < 8; ++p) {
        int idx = tid + p * 256;
        int r = (idx >> 4) & 127, c = idx & 15;
        cp16(sb + r * FST + c * 16,
             qH + ((size_t)(b * T_ + t0q + r) * NH_ + h) * HD_ + c * 8);
    }
    #pragma unroll
    for (int p = 0; p < 16; ++p) {
        int idx = tid + p * 256;
        int part = idx >> 11;
        int r = (idx >> 4) & 127, c = idx & 15;
        const __half* src = part ? vH : kH;
        cp16(sb + QT + part * KVP2 + r * FST + c * 16,
             src + ((size_t)(b * T_ + r) * NKV_ + kvh) * HD_ + c * 8);
    }
    CP_COMMIT();
    CP_WAIT0();
    __syncthreads();

    uint32_t QF[8][4];
    #pragma unroll
    for (int ks = 0; ks < 8; ++ks) {
        uint32_t ra = sb + (wid * 16 + (lane & 15)) * FST
                    + ks * 32 + ((lane >> 4) << 4);
        ldsm_x4(QF[ks], ra);
    }

    float m0 = NEG_INF, m1 = NEG_INF, l0 = 0.f, l1 = 0.f;
    float O[16][4];
    #pragma unroll
    for (int nt = 0; nt < 16; ++nt)
        #pragma unroll
        for (int j = 0; j < 4; ++j) O[nt][j] = 0.f;

    const int row_a = t0q + wid * 16 + (lane >> 2);

    for (int jt = 0; jt <= itq; ++jt) {
        const int buf = jt & 1;
        if (jt > 0) { CP_WAIT0(); __syncthreads(); }
        if (jt + 1 <= itq) {
            const int t0n = (jt + 1) * 128;
            #pragma unroll
            for (int p = 0; p < 16; ++p) {
                int idx = tid + p * 256;
                int part = idx >> 11;
                int r = (idx >> 4) & 127, c = idx & 15;
                const __half* src = part ? vH : kH;
                cp16(sb + QT + (buf ^ 1) * STG2 + part * KVP2 + r * FST + c * 16,
                     src + ((size_t)(b * T_ + t0n + r) * NKV_ + kvh) * HD_ + c * 8);
            }
            CP_COMMIT();
        }

        const uint32_t base_k = sb + QT + buf * STG2;
        const uint32_t base_v = base_k + KVP2;
        const int t0k = jt * 128;

        float S[16][4];
        #pragma unroll
        for (int nt = 0; nt < 16; ++nt)
            #pragma unroll
            for (int j = 0; j < 4; ++j) S[nt][j] = 0.f;

        #pragma unroll
        for (int ks = 0; ks < 8; ++ks) {
            const uint32_t rk = base_k + ks * 32 + (((lane >> 3) & 1) << 4)
                              + ((lane & 7) + ((lane >> 4) << 3)) * FST;
            uint32_t bh[2][4];
            ldsm_x4(bh[0], rk);
            #pragma unroll
            for (int ntp = 0; ntp < 8; ++ntp) {
                if (ntp < 7)
                    ldsm_x4(bh[(ntp + 1) & 1], rk + (ntp + 1) * 16 * FST);
                mma_f16(S[2 * ntp],     QF[ks], bh[ntp & 1]);
                mma_f16(S[2 * ntp + 1], QF[ks], bh[ntp & 1] + 2);
            }
        }

        const bool diag = (jt == itq);
        float ml0 = NEG_INF, ml1 = NEG_INF;
        #pragma unroll
        for (int nt = 0; nt < 16; ++nt) {
            int c = t0k + nt * 8 + 2 * (lane & 3);
            if (diag) {
                if (c     > row_a)     S[nt][0] = NEG_INF;
                if (c + 1 > row_a)     S[nt][1] = NEG_INF;
                if (c     > row_a + 8) S[nt][2] = NEG_INF;
                if (c + 1 > row_a + 8) S[nt][3] = NEG_INF;
            }
            ml0 = fmaxf(ml0, fmaxf(S[nt][0], S[nt][1]));
            ml1 = fmaxf(ml1, fmaxf(S[nt][2], S[nt][3]));
        }
        ml0 = fmaxf(ml0, __shfl_xor_sync(0xffffffffu, ml0, 1));
        ml0 = fmaxf(ml0, __shfl_xor_sync(0xffffffffu, ml0, 2));
        ml1 = fmaxf(ml1, __shfl_xor_sync(0xffffffffu, ml1, 1));
        ml1 = fmaxf(ml1, __shfl_xor_sync(0xffffffffu, ml1, 2));

        float mn0 = fmaxf(m0, ml0), mn1 = fmaxf(m1, ml1);
        float es0 = ex2(m0 - mn0);
        float es1 = ex2(m1 - mn1);
        m0 = mn0; m1 = mn1;
        #pragma unroll
        for (int nt = 0; nt < 16; ++nt) {
            O[nt][0] *= es0; O[nt][1] *= es0;
            O[nt][2] *= es1; O[nt][3] *= es1;
        }

        float sum0 = 0.f, sum1 = 0.f;
        #pragma unroll
        for (int half = 0; half < 2; ++half) {
            uint32_t PH[16];
            #pragma unroll
            for (int ntl = 0; ntl < 8; ++ntl) {
                int nt = half * 8 + ntl;
                float p0 = ex2(S[nt][0] - mn0);
                float p1 = ex2(S[nt][1] - mn0);
                float p2 = ex2(S[nt][2] - mn1);
                float p3 = ex2(S[nt][3] - mn1);
                sum0 += p0 + p1;  sum1 += p2 + p3;
                __half2 hA = __floats2half2_rn(p0, p1);
                __half2 hB = __floats2half2_rn(p2, p3);
                PH[2 * ntl]     = *(uint32_t*)&hA;
                PH[2 * ntl + 1] = *(uint32_t*)&hB;
            }
            #pragma unroll
            for (int kt = 0; kt < 4; ++kt) {
                uint32_t pa[4] = { PH[4*kt], PH[4*kt+1], PH[4*kt+2], PH[4*kt+3] };
                #pragma unroll
                for (int ntp = 0; ntp < 8; ++ntp) {
                    uint32_t bh[4];
                    uint32_t rv = base_v
                                + (half * 64 + kt * 16 + (lane & 7) + (lane & 8)) * FST
                                + ntp * 32 + ((lane >> 4) << 4);
                    ldsm_x4_t(bh, rv);
                    mma_f16(O[2 * ntp],     pa, bh);
                    mma_f16(O[2 * ntp + 1], pa, bh + 2);
                }
            }
        }
        sum0 += __shfl_xor_sync(0xffffffffu, sum0, 1);
        sum0 += __shfl_xor_sync(0xffffffffu, sum0, 2);
        sum1 += __shfl_xor_sync(0xffffffffu, sum1, 1);
        sum1 += __shfl_xor_sync(0xffffffffu, sum1, 2);
        l0 = l0 * es0 + sum0;
        l1 = l1 * es1 + sum1;
    }

    float inv0 = 1.f / l0, inv1 = 1.f / l1;
    #pragma unroll
    for (int nt = 0; nt < 16; ++nt) {
        int c = nt * 8 + 2 * (lane & 3);
        size_t baseA = ((size_t)(b * T_ + row_a) * NH_ + h) * HD_ + c;
        size_t baseB = ((size_t)(b * T_ + row_a + 8) * NH_ + h) * HD_ + c;
        __half2 uA = __floats2half2_rn(O[nt][0] * inv0, O[nt][1] * inv0);
        __half2 uB = __floats2half2_rn(O[nt][2] * inv1, O[nt][3] * inv1);
        *(uint32_t*)(y + baseA) = *(uint32_t*)&uA;
        *(uint32_t*)(y + baseB) = *(uint32_t*)&uB;
    }
}

// ---------------------------------------------------------------------------
extern "C" void kernel_launch(void* const* d_in, const int* in_sizes, int n_in,
                              void* d_out, int out_size)
{
    const float* x  = (const float*)d_in[0];
    const float* Wq = (const float*)d_in[1];
    const float* Wk = (const float*)d_in[2];
    const float* Wv = (const float*)d_in[3];
    const float* Wp = (const float*)d_in[4];
    const float* qg = (const float*)d_in[5];
    float* out = (float*)d_out;

    __half *xH, *wqH, *wkH, *wvH, *wpH, *qh16, *kh16, *vh16, *yH;
    cudaGetSymbolAddress((void**)&xH,  g_xH);
    cudaGetSymbolAddress((void**)&wqH, g_wqH);
    cudaGetSymbolAddress((void**)&wkH, g_wkH);
    cudaGetSymbolAddress((void**)&wvH, g_wvH);
    cudaGetSymbolAddress((void**)&wpH, g_wpH);
    cudaGetSymbolAddress((void**)&qh16, g_qH);
    cudaGetSymbolAddress((void**)&kh16, g_kH);
    cudaGetSymbolAddress((void**)&vh16, g_vH);
    cudaGetSymbolAddress((void**)&yH,  g_yH);

    cudaFuncSetAttribute(gemm_qkv, cudaFuncAttributeMaxDynamicSharedMemorySize, HSMEM);
    cudaFuncSetAttribute(gemm_out, cudaFuncAttributeMaxDynamicSharedMemorySize, HSMEM);
    cudaFuncSetAttribute(flash_mma, cudaFuncAttributeMaxDynamicSharedMemorySize, FSMEM2);

    rope_table_kernel<<<(T_ * 64 + 255) / 256, 256>>>();
    split_all_kernel<<<(SPLIT_TOT + 1023) / 1024, 256>>>(x, Wq, Wk, Wv, Wp);

    gemm_qkv<<<dim3(24, (B_ * T_) / 128), 512, HSMEM>>>(
        xH, wqH, wkH, wvH, qg, qh16, kh16, vh16);

    flash_mma<<<dim3(T_ / 128, NH_, B_), 256, FSMEM2>>>(qh16, kh16, vh16, yH);

    gemm_out<<<dim3(DIM_ / 128, (B_ * T_) / 128), 512, HSMEM>>>(
        yH, wpH, out, DIM_, DIM_);
}